// round 5
// baseline (speedup 1.0000x reference)
#include <cuda_runtime.h>
#include <cstdint>

// Problem dims
#define Bb 384
#define Ss 128
#define Ee 512
#define Hh 4
#define Dd 128
#define Mtot (Bb*Ss)   // 49152

// Scratch (device globals: allocation-free). Resolved via cudaGetSymbolAddress.
__device__ float g_q[(size_t)Mtot*Ee];
__device__ float g_k[(size_t)Mtot*Ee];
__device__ float g_v[(size_t)Mtot*Ee];
__device__ float g_att[(size_t)Mtot*Ee];

// ---------------- PTX mma m16n8k8 tf32 ----------------
// D = A(16x8, row) * B(8x8, col) + C, fp32 accum.
// lane -> g = lane>>2 (group), t = lane&3.
// A frag: a0=(g,t) a1=(g+8,t) a2=(g,t+4) a3=(g+8,t+4)
// B frag: b0=(k=t, n=g) b1=(k=t+4, n=g)
// C frag: c0=(g,2t) c1=(g,2t+1) c2=(g+8,2t) c3=(g+8,2t+1)
__device__ __forceinline__ void mma8(float* c, const uint32_t* a, const uint32_t* b) {
    asm volatile(
        "mma.sync.aligned.m16n8k8.row.col.f32.tf32.tf32.f32 "
        "{%0,%1,%2,%3}, {%4,%5,%6,%7}, {%8,%9}, {%0,%1,%2,%3};\n"
        : "+f"(c[0]), "+f"(c[1]), "+f"(c[2]), "+f"(c[3])
        : "r"(a[0]), "r"(a[1]), "r"(a[2]), "r"(a[3]), "r"(b[0]), "r"(b[1]));
}

__device__ __forceinline__ uint32_t tf32_hi(float x) {
    return __float_as_uint(x) & 0xFFFFE000u;
}
__device__ __forceinline__ uint32_t tf32_lo(float x, uint32_t hi) {
    return __float_as_uint(x - __uint_as_float(hi));
}

// ---------------- GEMM: C[M,N] = A[M,K] @ W[K,N] + bias ----------------
// M=49152, N=512, K=512. Block 128x128, BK=32, 256 threads (8 warps 4x2),
// warp tile 32x64 = 2(i) x 8(j) m16n8k8 frags. 3xTF32 split everywhere.
#define LDA 36    // BK + 4
#define LDB 132   // BN + 4

__global__ __launch_bounds__(256) void gemm_kernel(const float* __restrict__ A,
                                                   const float* __restrict__ W,
                                                   const float* __restrict__ bias,
                                                   float* __restrict__ C) {
    __shared__ float As[128*LDA];
    __shared__ float Ws[32*LDB];

    const int tid  = threadIdx.x;
    const int warp = tid >> 5;
    const int lane = tid & 31;
    const int g = lane >> 2, t = lane & 3;
    const int wm = (warp >> 1) * 32;
    const int wn = (warp & 1) * 64;
    const int bn = blockIdx.x * 128;   // N-tile fastest-varying -> A-tile L2 reuse
    const int bm = blockIdx.y * 128;

    float acc[2][8][4] = {};

    for (int k0 = 0; k0 < Ee; k0 += 32) {
        // A tile 128x32 = 1024 float4, 4 per thread
        #pragma unroll
        for (int it = 0; it < 4; it++) {
            int idx = tid + it*256;
            int r = idx >> 3, c = (idx & 7) << 2;
            float4 v = *(const float4*)(A + (size_t)(bm + r)*Ee + k0 + c);
            float* d = As + r*LDA + c;
            d[0]=v.x; d[1]=v.y; d[2]=v.z; d[3]=v.w;
        }
        // W tile 32x128 = 1024 float4, 4 per thread
        #pragma unroll
        for (int it = 0; it < 4; it++) {
            int idx = tid + it*256;
            int r = idx >> 5, c = (idx & 31) << 2;
            float4 v = *(const float4*)(W + (size_t)(k0 + r)*Ee + bn + c);
            float* d = Ws + r*LDB + c;
            d[0]=v.x; d[1]=v.y; d[2]=v.z; d[3]=v.w;
        }
        __syncthreads();

        #pragma unroll
        for (int kk = 0; kk < 32; kk += 8) {
            uint32_t ah[2][4], al[2][4];
            #pragma unroll
            for (int i = 0; i < 2; i++) {
                const float* p = As + (wm + i*16 + g)*LDA + kk + t;
                float a0 = p[0], a1 = p[8*LDA], a2 = p[4], a3 = p[8*LDA+4];
                ah[i][0]=tf32_hi(a0); al[i][0]=tf32_lo(a0, ah[i][0]);
                ah[i][1]=tf32_hi(a1); al[i][1]=tf32_lo(a1, ah[i][1]);
                ah[i][2]=tf32_hi(a2); al[i][2]=tf32_lo(a2, ah[i][2]);
                ah[i][3]=tf32_hi(a3); al[i][3]=tf32_lo(a3, ah[i][3]);
            }
            #pragma unroll
            for (int j = 0; j < 8; j++) {
                const float* p = Ws + (kk + t)*LDB + wn + j*8 + g;
                float b0 = p[0], b1 = p[4*LDB];
                uint32_t bh[2] = { tf32_hi(b0), tf32_hi(b1) };
                uint32_t bl[2] = { tf32_lo(b0, bh[0]), tf32_lo(b1, bh[1]) };
                #pragma unroll
                for (int i = 0; i < 2; i++) {
                    mma8(acc[i][j], ah[i], bh);
                    mma8(acc[i][j], ah[i], bl);
                    mma8(acc[i][j], al[i], bh);
                }
            }
        }
        __syncthreads();
    }

    // Epilogue: direct fragment stores (float2 pairs), add bias
    #pragma unroll
    for (int i = 0; i < 2; i++) {
        #pragma unroll
        for (int j = 0; j < 8; j++) {
            int row = bm + wm + i*16 + g;
            int col = bn + wn + j*8 + 2*t;
            float bz0 = bias[col], bz1 = bias[col+1];
            float2 v0 = { acc[i][j][0] + bz0, acc[i][j][1] + bz1 };
            float2 v1 = { acc[i][j][2] + bz0, acc[i][j][3] + bz1 };
            *(float2*)(C + (size_t)row*Ee + col)       = v0;
            *(float2*)(C + (size_t)(row + 8)*Ee + col) = v1;
        }
    }
}

// ---------------- Attention: one block per (b,h) ----------------
// scores = QK^T (3xTF32 split), row softmax, out = P V (3xTF32 split)
#define LDT 132  // Dd + 4

__global__ __launch_bounds__(256) void attn_kernel(const float* __restrict__ gq,
                                                   const float* __restrict__ gk,
                                                   const float* __restrict__ gv,
                                                   float* __restrict__ gatt) {
    extern __shared__ float sm[];
    float* sQ = sm;                    // [128][LDT]  (reused for V)
    float* sK = sm + Ss*LDT;
    float* sS = sm + 2*Ss*LDT;

    const int bh = blockIdx.x;
    const int b  = bh >> 2;
    const int h  = bh & 3;
    const int tid  = threadIdx.x;
    const int warp = tid >> 5;
    const int lane = tid & 31;
    const int g = lane >> 2, t = lane & 3;

    const float* qbase = gq + (size_t)b*Ss*Ee + h*Dd;
    const float* kbase = gk + (size_t)b*Ss*Ee + h*Dd;
    const float* vbase = gv + (size_t)b*Ss*Ee + h*Dd;

    // Load Q and K tiles: 128x128 fp32 = 4096 float4 each, 16 per thread
    #pragma unroll
    for (int it = 0; it < 16; it++) {
        int idx = tid + it*256;
        int r = idx >> 5, c = (idx & 31) << 2;
        float4 v = *(const float4*)(qbase + (size_t)r*Ee + c);
        float* d = sQ + r*LDT + c;
        d[0]=v.x; d[1]=v.y; d[2]=v.z; d[3]=v.w;
        v = *(const float4*)(kbase + (size_t)r*Ee + c);
        d = sK + r*LDT + c;
        d[0]=v.x; d[1]=v.y; d[2]=v.z; d[3]=v.w;
    }
    __syncthreads();

    float acc[16][4];

    // Scores (split): warp computes rows [warp*16, +16) x 128 cols
    #pragma unroll
    for (int j = 0; j < 16; j++) { acc[j][0]=0.f; acc[j][1]=0.f; acc[j][2]=0.f; acc[j][3]=0.f; }

    for (int kk = 0; kk < Dd; kk += 8) {
        const float* p = sQ + (warp*16 + g)*LDT + kk + t;
        float a0 = p[0], a1 = p[8*LDT], a2 = p[4], a3 = p[8*LDT+4];
        uint32_t ah[4] = { tf32_hi(a0), tf32_hi(a1), tf32_hi(a2), tf32_hi(a3) };
        uint32_t al[4] = { tf32_lo(a0, ah[0]), tf32_lo(a1, ah[1]),
                           tf32_lo(a2, ah[2]), tf32_lo(a3, ah[3]) };
        #pragma unroll
        for (int j = 0; j < 16; j++) {
            // B[k][n] = K[t_row = j*8+n][kk+k]
            const float* q = sK + (j*8 + g)*LDT + kk + t;
            float b0 = q[0], b1 = q[4];
            uint32_t bh[2] = { tf32_hi(b0), tf32_hi(b1) };
            uint32_t bl[2] = { tf32_lo(b0, bh[0]), tf32_lo(b1, bh[1]) };
            mma8(acc[j], ah, bh);
            mma8(acc[j], ah, bl);
            mma8(acc[j], al, bh);
        }
    }
    // Store scores to sS (float2 pairs)
    #pragma unroll
    for (int j = 0; j < 16; j++) {
        float* p = sS + (warp*16 + g)*LDT + j*8 + 2*t;
        *(float2*)p              = { acc[j][0], acc[j][1] };
        *(float2*)(p + 8*LDT)    = { acc[j][2], acc[j][3] };
    }
    __syncthreads();   // scores done; sQ free for reuse

    // Load V into sQ's buffer
    float* sV = sQ;
    #pragma unroll
    for (int it = 0; it < 16; it++) {
        int idx = tid + it*256;
        int r = idx >> 5, c = (idx & 31) << 2;
        float4 v = *(const float4*)(vbase + (size_t)r*Ee + c);
        float* d = sV + r*LDT + c;
        d[0]=v.x; d[1]=v.y; d[2]=v.z; d[3]=v.w;
    }

    // Row softmax: each warp owns 16 rows; lane covers cols {lane, +32, +64, +96}
    #pragma unroll 1
    for (int rr = 0; rr < 16; rr++) {
        float* row = sS + (warp*16 + rr)*LDT;
        float v0 = row[lane], v1 = row[lane+32], v2 = row[lane+64], v3 = row[lane+96];
        float m = fmaxf(fmaxf(v0, v1), fmaxf(v2, v3));
        #pragma unroll
        for (int off = 16; off > 0; off >>= 1)
            m = fmaxf(m, __shfl_xor_sync(0xFFFFFFFFu, m, off));
        v0 = __expf(v0 - m); v1 = __expf(v1 - m); v2 = __expf(v2 - m); v3 = __expf(v3 - m);
        float s = v0 + v1 + v2 + v3;
        #pragma unroll
        for (int off = 16; off > 0; off >>= 1)
            s += __shfl_xor_sync(0xFFFFFFFFu, s, off);
        float inv = 1.0f / s;
        row[lane]    = v0 * inv;
        row[lane+32] = v1 * inv;
        row[lane+64] = v2 * inv;
        row[lane+96] = v3 * inv;
    }
    __syncthreads();   // V loaded + all weights normalized

    // Out = P @ V (3xTF32 split)
    #pragma unroll
    for (int j = 0; j < 16; j++) { acc[j][0]=0.f; acc[j][1]=0.f; acc[j][2]=0.f; acc[j][3]=0.f; }

    for (int kk = 0; kk < Ss; kk += 8) {
        const float* p = sS + (warp*16 + g)*LDT + kk + t;
        float a0 = p[0], a1 = p[8*LDT], a2 = p[4], a3 = p[8*LDT+4];
        uint32_t ah[4] = { tf32_hi(a0), tf32_hi(a1), tf32_hi(a2), tf32_hi(a3) };
        uint32_t al[4] = { tf32_lo(a0, ah[0]), tf32_lo(a1, ah[1]),
                           tf32_lo(a2, ah[2]), tf32_lo(a3, ah[3]) };
        #pragma unroll
        for (int j = 0; j < 16; j++) {
            // B[k][n] = V[kk+k][j*8+n]
            const float* q = sV + (kk + t)*LDT + j*8 + g;
            float b0 = q[0], b1 = q[4*LDT];
            uint32_t bh[2] = { tf32_hi(b0), tf32_hi(b1) };
            uint32_t bl[2] = { tf32_lo(b0, bh[0]), tf32_lo(b1, bh[1]) };
            mma8(acc[j], ah, bh);
            mma8(acc[j], ah, bl);
            mma8(acc[j], al, bh);
        }
    }

    // Store to g_att: rows b*Ss + warp*16 + g (+8), cols h*Dd + j*8 + 2t
    #pragma unroll
    for (int j = 0; j < 16; j++) {
        size_t row = (size_t)(b*Ss + warp*16 + g);
        int col = h*Dd + j*8 + 2*t;
        *(float2*)(gatt + row*Ee + col)       = { acc[j][0], acc[j][1] };
        *(float2*)(gatt + (row + 8)*Ee + col) = { acc[j][2], acc[j][3] };
    }
}

// ---------------- Launch ----------------
extern "C" void kernel_launch(void* const* d_in, const int* in_sizes, int n_in,
                              void* d_out, int out_size) {
    const float* x  = (const float*)d_in[0];
    const float* Wq = (const float*)d_in[1];
    const float* bq = (const float*)d_in[2];
    const float* Wk = (const float*)d_in[3];
    const float* bk = (const float*)d_in[4];
    const float* Wv = (const float*)d_in[5];
    const float* bv = (const float*)d_in[6];
    const float* Wo = (const float*)d_in[7];
    const float* bo = (const float*)d_in[8];
    float* y = (float*)d_out;

    float *q, *k, *v, *att;
    cudaGetSymbolAddress((void**)&q,   g_q);
    cudaGetSymbolAddress((void**)&k,   g_k);
    cudaGetSymbolAddress((void**)&v,   g_v);
    cudaGetSymbolAddress((void**)&att, g_att);

    const int attn_smem = 3 * Ss * LDT * (int)sizeof(float);   // 202752 bytes
    cudaFuncSetAttribute(attn_kernel, cudaFuncAttributeMaxDynamicSharedMemorySize, attn_smem);

    dim3 gg(Ee/128, Mtot/128);     // (4, 384): N-tile fastest for A-tile L2 reuse

    gemm_kernel<<<gg, 256>>>(x, Wq, bq, q);
    gemm_kernel<<<gg, 256>>>(x, Wk, bk, k);
    gemm_kernel<<<gg, 256>>>(x, Wv, bv, v);

    attn_kernel<<<Bb*Hh, 256, attn_smem>>>(q, k, v, att);   // 1536 blocks, one per (b,h)

    gemm_kernel<<<gg, 256>>>(att, Wo, bo, y);
}

// round 6
// speedup vs baseline: 1.0587x; 1.0587x over previous
#include <cuda_runtime.h>
#include <cstdint>

// Problem dims
#define Bb 384
#define Ss 128
#define Ee 512
#define Hh 4
#define Dd 128
#define Mtot (Bb*Ss)   // 49152

// Scratch (device globals: allocation-free). Resolved via cudaGetSymbolAddress.
__device__ float g_q[(size_t)Mtot*Ee];
__device__ float g_k[(size_t)Mtot*Ee];
__device__ float g_v[(size_t)Mtot*Ee];
__device__ float g_att[(size_t)Mtot*Ee];

// ---------------- PTX mma m16n8k8 tf32 ----------------
// lane -> g = lane>>2, t = lane&3.
// A frag: a0=(g,t) a1=(g+8,t) a2=(g,t+4) a3=(g+8,t+4)
// B frag: b0=(k=t, n=g) b1=(k=t+4, n=g)
// C frag: c0=(g,2t) c1=(g,2t+1) c2=(g+8,2t) c3=(g+8,2t+1)
__device__ __forceinline__ void mma8(float* c, const uint32_t* a, const uint32_t* b) {
    asm volatile(
        "mma.sync.aligned.m16n8k8.row.col.f32.tf32.tf32.f32 "
        "{%0,%1,%2,%3}, {%4,%5,%6,%7}, {%8,%9}, {%0,%1,%2,%3};\n"
        : "+f"(c[0]), "+f"(c[1]), "+f"(c[2]), "+f"(c[3])
        : "r"(a[0]), "r"(a[1]), "r"(a[2]), "r"(a[3]), "r"(b[0]), "r"(b[1]));
}

__device__ __forceinline__ uint32_t tf32_hi(float x) {
    return __float_as_uint(x) & 0xFFFFE000u;
}
__device__ __forceinline__ uint32_t tf32_lo(float x, uint32_t hi) {
    return __float_as_uint(x - __uint_as_float(hi));
}

__device__ __forceinline__ void cpasync16(float* dst, const float* src) {
    uint32_t s = (uint32_t)__cvta_generic_to_shared(dst);
    asm volatile("cp.async.cg.shared.global [%0], [%1], 16;\n" :: "r"(s), "l"(src));
}

// ---------------- GEMM body: C[.,N] += A[.,K] @ W[K,N] + bias ----------------
// Block tile 128x128, BK=32, 256 threads (8 warps 4x2), warp 32x64,
// 3xTF32 split, cp.async 2-stage pipeline.
#define LDA 36     // 32+4; 144B row stride (16B-aligned)
#define LDB 132    // 128+4; 528B row stride (16B-aligned)
#define ASTG (128*LDA)   // 4608 floats per stage
#define WSTG (32*LDB)    // 4224 floats per stage
#define GEMM_SMEM ((2*ASTG + 2*WSTG) * 4)   // 70656 bytes

__device__ __forceinline__ void gemm_body(const float* __restrict__ A,
                                          const float* __restrict__ W,
                                          const float* __restrict__ bias,
                                          float* __restrict__ C,
                                          int bm, int bn, float* smem) {
    float* Asm = smem;               // [2][ASTG]
    float* Wsm = smem + 2*ASTG;      // [2][WSTG]

    const int tid  = threadIdx.x;
    const int warp = tid >> 5;
    const int lane = tid & 31;
    const int g = lane >> 2, t = lane & 3;
    const int wm = (warp >> 1) * 32;
    const int wn = (warp & 1) * 64;

    // Per-thread load coords (fixed across stages)
    const int ar = tid >> 3, ac = (tid & 7) << 2;       // A: 4 rows apart per it
    const int wr = tid >> 5, wc = (tid & 31) << 2;      // W: 8 rows apart per it

    float acc[2][8][4] = {};

    // stage issue: A tile 128x32 (4 cp/thread), W tile 32x128 (4 cp/thread)
    #define ISSUE(k0, s)  do {                                                  \
        float* as_ = Asm + (s)*ASTG;                                            \
        float* ws_ = Wsm + (s)*WSTG;                                            \
        _Pragma("unroll")                                                       \
        for (int it = 0; it < 4; it++)                                          \
            cpasync16(as_ + (ar + it*32)*LDA + ac,                              \
                      A + (size_t)(bm + ar + it*32)*Ee + (k0) + ac);            \
        _Pragma("unroll")                                                       \
        for (int it = 0; it < 4; it++)                                          \
            cpasync16(ws_ + (wr + it*8)*LDB + wc,                               \
                      W + (size_t)((k0) + wr + it*8)*Ee + bn + wc);             \
        asm volatile("cp.async.commit_group;\n");                               \
    } while (0)

    ISSUE(0, 0);

    for (int ki = 0; ki < Ee/32; ki++) {
        if (ki + 1 < Ee/32) {
            ISSUE((ki+1)*32, (ki+1) & 1);
            asm volatile("cp.async.wait_group 1;\n");
        } else {
            asm volatile("cp.async.wait_group 0;\n");
        }
        __syncthreads();

        const float* as_ = Asm + (ki & 1)*ASTG;
        const float* ws_ = Wsm + (ki & 1)*WSTG;

        #pragma unroll
        for (int kk = 0; kk < 32; kk += 8) {
            uint32_t ah[2][4], al[2][4];
            #pragma unroll
            for (int i = 0; i < 2; i++) {
                const float* p = as_ + (wm + i*16 + g)*LDA + kk + t;
                float a0 = p[0], a1 = p[8*LDA], a2 = p[4], a3 = p[8*LDA+4];
                ah[i][0]=tf32_hi(a0); al[i][0]=tf32_lo(a0, ah[i][0]);
                ah[i][1]=tf32_hi(a1); al[i][1]=tf32_lo(a1, ah[i][1]);
                ah[i][2]=tf32_hi(a2); al[i][2]=tf32_lo(a2, ah[i][2]);
                ah[i][3]=tf32_hi(a3); al[i][3]=tf32_lo(a3, ah[i][3]);
            }
            #pragma unroll
            for (int j = 0; j < 8; j++) {
                const float* p = ws_ + (kk + t)*LDB + wn + j*8 + g;
                float b0 = p[0], b1 = p[4*LDB];
                uint32_t bh[2] = { tf32_hi(b0), tf32_hi(b1) };
                uint32_t bl[2] = { tf32_lo(b0, bh[0]), tf32_lo(b1, bh[1]) };
                #pragma unroll
                for (int i = 0; i < 2; i++) {
                    mma8(acc[i][j], ah[i], bh);
                    mma8(acc[i][j], ah[i], bl);
                    mma8(acc[i][j], al[i], bh);
                }
            }
        }
        __syncthreads();
    }
    #undef ISSUE

    // Epilogue: direct fragment stores (float2 pairs), add bias
    #pragma unroll
    for (int i = 0; i < 2; i++) {
        #pragma unroll
        for (int j = 0; j < 8; j++) {
            int row = bm + wm + i*16 + g;
            int col = bn + wn + j*8 + 2*t;
            float bz0 = bias[col], bz1 = bias[col+1];
            float2 v0 = { acc[i][j][0] + bz0, acc[i][j][1] + bz1 };
            float2 v1 = { acc[i][j][2] + bz0, acc[i][j][3] + bz1 };
            *(float2*)(C + (size_t)row*Ee + col)       = v0;
            *(float2*)(C + (size_t)(row + 8)*Ee + col) = v1;
        }
    }
}

// Fused QKV: grid (12, 384); x = mat*? -> mat = x%3, ntile = x/3 (x-adjacent
// CTAs share the same A row-block -> x-tile L2 reuse across all 3 mats).
__global__ __launch_bounds__(256, 2) void qkv_kernel(const float* __restrict__ x,
        const float* __restrict__ Wq, const float* __restrict__ bq,
        const float* __restrict__ Wk, const float* __restrict__ bk,
        const float* __restrict__ Wv, const float* __restrict__ bv,
        float* __restrict__ q, float* __restrict__ k, float* __restrict__ v) {
    extern __shared__ float smem[];
    const int mat = blockIdx.x % 3;
    const int bn  = (blockIdx.x / 3) * 128;
    const int bm  = blockIdx.y * 128;
    const float* W; const float* bias; float* C;
    if (mat == 0)      { W = Wq; bias = bq; C = q; }
    else if (mat == 1) { W = Wk; bias = bk; C = k; }
    else               { W = Wv; bias = bv; C = v; }
    gemm_body(x, W, bias, C, bm, bn, smem);
}

__global__ __launch_bounds__(256, 2) void out_kernel(const float* __restrict__ att,
        const float* __restrict__ Wo, const float* __restrict__ bo,
        float* __restrict__ y) {
    extern __shared__ float smem[];
    gemm_body(att, Wo, bo, y, blockIdx.y * 128, blockIdx.x * 128, smem);
}

// ---------------- Attention: one block per (b,h) (unchanged, known-good) ----
#define LDT 132  // Dd + 4

__global__ __launch_bounds__(256) void attn_kernel(const float* __restrict__ gq,
                                                   const float* __restrict__ gk,
                                                   const float* __restrict__ gv,
                                                   float* __restrict__ gatt) {
    extern __shared__ float sm[];
    float* sQ = sm;                    // [128][LDT]  (reused for V)
    float* sK = sm + Ss*LDT;
    float* sS = sm + 2*Ss*LDT;

    const int bh = blockIdx.x;
    const int b  = bh >> 2;
    const int h  = bh & 3;
    const int tid  = threadIdx.x;
    const int warp = tid >> 5;
    const int lane = tid & 31;
    const int g = lane >> 2, t = lane & 3;

    const float* qbase = gq + (size_t)b*Ss*Ee + h*Dd;
    const float* kbase = gk + (size_t)b*Ss*Ee + h*Dd;
    const float* vbase = gv + (size_t)b*Ss*Ee + h*Dd;

    #pragma unroll
    for (int it = 0; it < 16; it++) {
        int idx = tid + it*256;
        int r = idx >> 5, c = (idx & 31) << 2;
        float4 v = *(const float4*)(qbase + (size_t)r*Ee + c);
        float* d = sQ + r*LDT + c;
        d[0]=v.x; d[1]=v.y; d[2]=v.z; d[3]=v.w;
        v = *(const float4*)(kbase + (size_t)r*Ee + c);
        d = sK + r*LDT + c;
        d[0]=v.x; d[1]=v.y; d[2]=v.z; d[3]=v.w;
    }
    __syncthreads();

    float acc[16][4];

    #pragma unroll
    for (int j = 0; j < 16; j++) { acc[j][0]=0.f; acc[j][1]=0.f; acc[j][2]=0.f; acc[j][3]=0.f; }

    for (int kk = 0; kk < Dd; kk += 8) {
        const float* p = sQ + (warp*16 + g)*LDT + kk + t;
        float a0 = p[0], a1 = p[8*LDT], a2 = p[4], a3 = p[8*LDT+4];
        uint32_t ah[4] = { tf32_hi(a0), tf32_hi(a1), tf32_hi(a2), tf32_hi(a3) };
        uint32_t al[4] = { tf32_lo(a0, ah[0]), tf32_lo(a1, ah[1]),
                           tf32_lo(a2, ah[2]), tf32_lo(a3, ah[3]) };
        #pragma unroll
        for (int j = 0; j < 16; j++) {
            const float* q = sK + (j*8 + g)*LDT + kk + t;
            float b0 = q[0], b1 = q[4];
            uint32_t bh[2] = { tf32_hi(b0), tf32_hi(b1) };
            uint32_t bl[2] = { tf32_lo(b0, bh[0]), tf32_lo(b1, bh[1]) };
            mma8(acc[j], ah, bh);
            mma8(acc[j], ah, bl);
            mma8(acc[j], al, bh);
        }
    }
    #pragma unroll
    for (int j = 0; j < 16; j++) {
        float* p = sS + (warp*16 + g)*LDT + j*8 + 2*t;
        *(float2*)p              = { acc[j][0], acc[j][1] };
        *(float2*)(p + 8*LDT)    = { acc[j][2], acc[j][3] };
    }
    __syncthreads();

    float* sV = sQ;
    #pragma unroll
    for (int it = 0; it < 16; it++) {
        int idx = tid + it*256;
        int r = idx >> 5, c = (idx & 31) << 2;
        float4 v = *(const float4*)(vbase + (size_t)r*Ee + c);
        float* d = sV + r*LDT + c;
        d[0]=v.x; d[1]=v.y; d[2]=v.z; d[3]=v.w;
    }

    #pragma unroll 1
    for (int rr = 0; rr < 16; rr++) {
        float* row = sS + (warp*16 + rr)*LDT;
        float v0 = row[lane], v1 = row[lane+32], v2 = row[lane+64], v3 = row[lane+96];
        float m = fmaxf(fmaxf(v0, v1), fmaxf(v2, v3));
        #pragma unroll
        for (int off = 16; off > 0; off >>= 1)
            m = fmaxf(m, __shfl_xor_sync(0xFFFFFFFFu, m, off));
        v0 = __expf(v0 - m); v1 = __expf(v1 - m); v2 = __expf(v2 - m); v3 = __expf(v3 - m);
        float s = v0 + v1 + v2 + v3;
        #pragma unroll
        for (int off = 16; off > 0; off >>= 1)
            s += __shfl_xor_sync(0xFFFFFFFFu, s, off);
        float inv = 1.0f / s;
        row[lane]    = v0 * inv;
        row[lane+32] = v1 * inv;
        row[lane+64] = v2 * inv;
        row[lane+96] = v3 * inv;
    }
    __syncthreads();

    #pragma unroll
    for (int j = 0; j < 16; j++) { acc[j][0]=0.f; acc[j][1]=0.f; acc[j][2]=0.f; acc[j][3]=0.f; }

    for (int kk = 0; kk < Ss; kk += 8) {
        const float* p = sS + (warp*16 + g)*LDT + kk + t;
        float a0 = p[0], a1 = p[8*LDT], a2 = p[4], a3 = p[8*LDT+4];
        uint32_t ah[4] = { tf32_hi(a0), tf32_hi(a1), tf32_hi(a2), tf32_hi(a3) };
        uint32_t al[4] = { tf32_lo(a0, ah[0]), tf32_lo(a1, ah[1]),
                           tf32_lo(a2, ah[2]), tf32_lo(a3, ah[3]) };
        #pragma unroll
        for (int j = 0; j < 16; j++) {
            const float* q = sV + (kk + t)*LDT + j*8 + g;
            float b0 = q[0], b1 = q[4*LDT];
            uint32_t bh[2] = { tf32_hi(b0), tf32_hi(b1) };
            uint32_t bl[2] = { tf32_lo(b0, bh[0]), tf32_lo(b1, bh[1]) };
            mma8(acc[j], ah, bh);
            mma8(acc[j], ah, bl);
            mma8(acc[j], al, bh);
        }
    }

    #pragma unroll
    for (int j = 0; j < 16; j++) {
        size_t row = (size_t)(b*Ss + warp*16 + g);
        int col = h*Dd + j*8 + 2*t;
        *(float2*)(gatt + row*Ee + col)       = { acc[j][0], acc[j][1] };
        *(float2*)(gatt + (row + 8)*Ee + col) = { acc[j][2], acc[j][3] };
    }
}

// ---------------- Launch ----------------
extern "C" void kernel_launch(void* const* d_in, const int* in_sizes, int n_in,
                              void* d_out, int out_size) {
    const float* x  = (const float*)d_in[0];
    const float* Wq = (const float*)d_in[1];
    const float* bq = (const float*)d_in[2];
    const float* Wk = (const float*)d_in[3];
    const float* bk = (const float*)d_in[4];
    const float* Wv = (const float*)d_in[5];
    const float* bv = (const float*)d_in[6];
    const float* Wo = (const float*)d_in[7];
    const float* bo = (const float*)d_in[8];
    float* y = (float*)d_out;

    float *q, *k, *v, *att;
    cudaGetSymbolAddress((void**)&q,   g_q);
    cudaGetSymbolAddress((void**)&k,   g_k);
    cudaGetSymbolAddress((void**)&v,   g_v);
    cudaGetSymbolAddress((void**)&att, g_att);

    const int attn_smem = 3 * Ss * LDT * (int)sizeof(float);   // 202752 bytes
    cudaFuncSetAttribute(attn_kernel, cudaFuncAttributeMaxDynamicSharedMemorySize, attn_smem);
    cudaFuncSetAttribute(qkv_kernel,  cudaFuncAttributeMaxDynamicSharedMemorySize, GEMM_SMEM);
    cudaFuncSetAttribute(out_kernel,  cudaFuncAttributeMaxDynamicSharedMemorySize, GEMM_SMEM);

    dim3 gqkv(12, Mtot/128);           // 3 mats x 4 N-tiles, x fastest
    qkv_kernel<<<gqkv, 256, GEMM_SMEM>>>(x, Wq, bq, Wk, bk, Wv, bv, q, k, v);

    attn_kernel<<<Bb*Hh, 256, attn_smem>>>(q, k, v, att);

    dim3 gout(Ee/128, Mtot/128);
    out_kernel<<<gout, 256, GEMM_SMEM>>>(att, Wo, bo, y);
}

// round 7
// speedup vs baseline: 1.5024x; 1.4190x over previous
#include <cuda_runtime.h>
#include <cstdint>

// Problem dims
#define Bb 384
#define Ss 128
#define Ee 512
#define Hh 4
#define Dd 128
#define Mtot (Bb*Ss)   // 49152

// Scratch (device globals: allocation-free). Resolved via cudaGetSymbolAddress.
__device__ float g_q[(size_t)Mtot*Ee];
__device__ float g_k[(size_t)Mtot*Ee];
__device__ float g_v[(size_t)Mtot*Ee];
__device__ float g_att[(size_t)Mtot*Ee];

// ---------------- PTX mma helpers ----------------
// tf32 m16n8k8 (used by attn kernel, unchanged)
__device__ __forceinline__ void mma8(float* c, const uint32_t* a, const uint32_t* b) {
    asm volatile(
        "mma.sync.aligned.m16n8k8.row.col.f32.tf32.tf32.f32 "
        "{%0,%1,%2,%3}, {%4,%5,%6,%7}, {%8,%9}, {%0,%1,%2,%3};\n"
        : "+f"(c[0]), "+f"(c[1]), "+f"(c[2]), "+f"(c[3])
        : "r"(a[0]), "r"(a[1]), "r"(a[2]), "r"(a[3]), "r"(b[0]), "r"(b[1]));
}

// bf16 m16n8k16 (GEMMs)
__device__ __forceinline__ void mma16(float* c, const uint32_t* a, const uint32_t* b) {
    asm volatile(
        "mma.sync.aligned.m16n8k16.row.col.f32.bf16.bf16.f32 "
        "{%0,%1,%2,%3}, {%4,%5,%6,%7}, {%8,%9}, {%0,%1,%2,%3};\n"
        : "+f"(c[0]), "+f"(c[1]), "+f"(c[2]), "+f"(c[3])
        : "r"(a[0]), "r"(a[1]), "r"(a[2]), "r"(a[3]), "r"(b[0]), "r"(b[1]));
}

__device__ __forceinline__ void ldsm_x4(uint32_t* r, uint32_t saddr) {
    asm volatile("ldmatrix.sync.aligned.m8n8.x4.shared.b16 {%0,%1,%2,%3}, [%4];\n"
        : "=r"(r[0]), "=r"(r[1]), "=r"(r[2]), "=r"(r[3]) : "r"(saddr));
}
__device__ __forceinline__ void ldsm_x2(uint32_t* r, uint32_t saddr) {
    asm volatile("ldmatrix.sync.aligned.m8n8.x2.shared.b16 {%0,%1}, [%2];\n"
        : "=r"(r[0]), "=r"(r[1]) : "r"(saddr));
}

__device__ __forceinline__ uint32_t tf32_hi(float x) {
    return __float_as_uint(x) & 0xFFFFE000u;
}
__device__ __forceinline__ uint32_t tf32_lo(float x, uint32_t hi) {
    return __float_as_uint(x - __uint_as_float(hi));
}

// Split two fp32 into packed bf16x2 hi (rn) and packed bf16x2 lo (residual).
// Packed order: x0 in low 16 bits, x1 in high (matches smem col c, c+1).
__device__ __forceinline__ void split2(float x0, float x1, uint32_t& hi, uint32_t& lo) {
    asm("cvt.rn.bf16x2.f32 %0, %1, %2;" : "=r"(hi) : "f"(x1), "f"(x0));
    float r0 = x0 - __uint_as_float(hi << 16);
    float r1 = x1 - __uint_as_float(hi & 0xFFFF0000u);
    asm("cvt.rn.bf16x2.f32 %0, %1, %2;" : "=r"(lo) : "f"(r1), "f"(r0));
}

__device__ __forceinline__ void cpasync16(float* dst, const float* src) {
    uint32_t s = (uint32_t)__cvta_generic_to_shared(dst);
    asm volatile("cp.async.cg.shared.global [%0], [%1], 16;\n" :: "r"(s), "l"(src));
}

// ---------------- GEMM: C[M,N] = A[M,K] @ W[K,N] + bias ----------------
// Block 128x128, BK=32, 256 threads (8 warps 4x2), warp 32x64.
// cp.async fp32 2-stage pipeline -> per-stage bf16 hi/lo conversion ->
// 3xBF16-split mma m16n8k16 (half the tensor instructions of 3xTF32 at k8).
#define LDA 36     // fp32 A stage stride (144B, 16B-aligned)
#define LDB 132    // fp32 W stage stride (528B, 16B-aligned)
#define ASTG (128*LDA)   // 4608 floats
#define WSTG (32*LDB)    // 4224 floats
#define LDH  20          // bf16 tile stride in 32-bit words (40 bf16 = 80B; conflict-free)
#define HTW  (128*LDH)   // words per bf16 tile = 2560
// float-offsets of the bf16 regions inside the smem pool
#define AHIW (2*ASTG + 2*WSTG)       // 17664
#define ALOW (AHIW + HTW)            // 20224
#define WTHI (ALOW + HTW)            // 22784
#define WTLO (WTHI + HTW)            // 25344
#define GEMM_SMEM ((WTLO + HTW) * 4) // 111616 bytes

__device__ __forceinline__ void gemm_body(const float* __restrict__ A,
                                          const float* __restrict__ W,
                                          const float* __restrict__ bias,
                                          float* __restrict__ C,
                                          int bm, int bn, float* smem) {
    float* Asm = smem;               // [2][ASTG] fp32 stages
    float* Wsm = smem + 2*ASTG;      // [2][WSTG]
    uint32_t* ah_w = (uint32_t*)(smem + AHIW);   // A hi  [128][LDH] words
    uint32_t* al_w = (uint32_t*)(smem + ALOW);   // A lo
    uint32_t* wh_w = (uint32_t*)(smem + WTHI);   // W^T hi [n:128][LDH]
    uint32_t* wl_w = (uint32_t*)(smem + WTLO);   // W^T lo

    const int tid  = threadIdx.x;
    const int warp = tid >> 5;
    const int lane = tid & 31;
    const int g = lane >> 2, t = lane & 3;
    const int wm = (warp >> 1) * 32;
    const int wn = (warp & 1) * 64;

    // cp.async per-thread coords
    const int ar = tid >> 3, ac = (tid & 7) << 2;     // A: rows ar+32*it, 4 cols
    const int wr = tid >> 5, wc = (tid & 31) << 2;    // W: rows wr+8*it, 4 cols

    // ldmatrix lane->address mapping
    const int arow = lane & 15;
    const int acol = ((lane >> 4) & 1) * 8;
    const int brow = lane & 7;
    const int bcol = ((lane >> 3) & 1) * 8;

    const uint32_t ah_b = (uint32_t)__cvta_generic_to_shared(ah_w);
    const uint32_t al_b = (uint32_t)__cvta_generic_to_shared(al_w);
    const uint32_t wh_b = (uint32_t)__cvta_generic_to_shared(wh_w);
    const uint32_t wl_b = (uint32_t)__cvta_generic_to_shared(wl_w);

    float acc[2][8][4] = {};

    #define ISSUE(k0, s)  do {                                                  \
        float* as_ = Asm + (s)*ASTG;                                            \
        float* ws_ = Wsm + (s)*WSTG;                                            \
        _Pragma("unroll")                                                       \
        for (int it = 0; it < 4; it++)                                          \
            cpasync16(as_ + (ar + it*32)*LDA + ac,                              \
                      A + (size_t)(bm + ar + it*32)*Ee + (k0) + ac);            \
        _Pragma("unroll")                                                       \
        for (int it = 0; it < 4; it++)                                          \
            cpasync16(ws_ + (wr + it*8)*LDB + wc,                               \
                      W + (size_t)((k0) + wr + it*8)*Ee + bn + wc);             \
        asm volatile("cp.async.commit_group;\n");                               \
    } while (0)

    ISSUE(0, 0);

    for (int ki = 0; ki < Ee/32; ki++) {
        if (ki + 1 < Ee/32) {
            ISSUE((ki+1)*32, (ki+1) & 1);
            asm volatile("cp.async.wait_group 1;\n");
        } else {
            asm volatile("cp.async.wait_group 0;\n");
        }
        __syncthreads();   // stage ki visible; also fences prev iter's mma reads

        const float* as_ = Asm + (ki & 1)*ASTG;
        const float* ws_ = Wsm + (ki & 1)*WSTG;

        // ---- convert A tile: fp32 [r][k] -> bf16 hi/lo [r][k] ----
        #pragma unroll
        for (int it = 0; it < 4; it++) {
            int r = ar + it*32;
            float4 v = *(const float4*)(as_ + r*LDA + ac);
            uint32_t h0, l0, h1, l1;
            split2(v.x, v.y, h0, l0);
            split2(v.z, v.w, h1, l1);
            int o = r*LDH + (ac >> 1);
            ah_w[o] = h0; ah_w[o+1] = h1;
            al_w[o] = l0; al_w[o+1] = l1;
        }
        // ---- convert W tile: fp32 [k][n] -> transposed bf16 hi/lo [n][k] ----
        #pragma unroll
        for (int it = 0; it < 4; it++) {
            int unit = tid + it*256;             // 1024 units of 4 k-values
            int n = unit & 127, k0 = (unit >> 7) << 2;
            float c0 = ws_[(k0  )*LDB + n];
            float c1 = ws_[(k0+1)*LDB + n];
            float c2 = ws_[(k0+2)*LDB + n];
            float c3 = ws_[(k0+3)*LDB + n];
            uint32_t h0, l0, h1, l1;
            split2(c0, c1, h0, l0);
            split2(c2, c3, h1, l1);
            int o = n*LDH + (k0 >> 1);
            wh_w[o] = h0; wh_w[o+1] = h1;
            wl_w[o] = l0; wl_w[o+1] = l1;
        }
        __syncthreads();

        // ---- mma over k16 slices ----
        #pragma unroll
        for (int kk = 0; kk < 32; kk += 16) {
            uint32_t AH[2][4], AL[2][4];
            #pragma unroll
            for (int i = 0; i < 2; i++) {
                uint32_t off = ((wm + i*16 + arow)*40 + kk + acol) * 2;
                ldsm_x4(AH[i], ah_b + off);
                ldsm_x4(AL[i], al_b + off);
            }
            #pragma unroll
            for (int j = 0; j < 8; j++) {
                uint32_t BH[2], BL[2];
                uint32_t off = ((wn + j*8 + brow)*40 + kk + bcol) * 2;
                ldsm_x2(BH, wh_b + off);
                ldsm_x2(BL, wl_b + off);
                #pragma unroll
                for (int i = 0; i < 2; i++) {
                    mma16(acc[i][j], AH[i], BH);
                    mma16(acc[i][j], AH[i], BL);
                    mma16(acc[i][j], AL[i], BH);
                }
            }
        }
    }
    #undef ISSUE
    __syncthreads();

    // Epilogue: direct fragment stores (float2 pairs), add bias
    #pragma unroll
    for (int i = 0; i < 2; i++) {
        #pragma unroll
        for (int j = 0; j < 8; j++) {
            int row = bm + wm + i*16 + g;
            int col = bn + wn + j*8 + 2*t;
            float bz0 = bias[col], bz1 = bias[col+1];
            float2 v0 = { acc[i][j][0] + bz0, acc[i][j][1] + bz1 };
            float2 v1 = { acc[i][j][2] + bz0, acc[i][j][3] + bz1 };
            *(float2*)(C + (size_t)row*Ee + col)       = v0;
            *(float2*)(C + (size_t)(row + 8)*Ee + col) = v1;
        }
    }
}

// Fused QKV: grid (12, 384); mat = x%3, N-tile = x/3 (x-adjacent CTAs share A rows)
__global__ __launch_bounds__(256, 2) void qkv_kernel(const float* __restrict__ x,
        const float* __restrict__ Wq, const float* __restrict__ bq,
        const float* __restrict__ Wk, const float* __restrict__ bk,
        const float* __restrict__ Wv, const float* __restrict__ bv,
        float* __restrict__ q, float* __restrict__ k, float* __restrict__ v) {
    extern __shared__ float smem[];
    const int mat = blockIdx.x % 3;
    const int bn  = (blockIdx.x / 3) * 128;
    const int bm  = blockIdx.y * 128;
    const float* W; const float* bias; float* C;
    if (mat == 0)      { W = Wq; bias = bq; C = q; }
    else if (mat == 1) { W = Wk; bias = bk; C = k; }
    else               { W = Wv; bias = bv; C = v; }
    gemm_body(x, W, bias, C, bm, bn, smem);
}

__global__ __launch_bounds__(256, 2) void out_kernel(const float* __restrict__ att,
        const float* __restrict__ Wo, const float* __restrict__ bo,
        float* __restrict__ y) {
    extern __shared__ float smem[];
    gemm_body(att, Wo, bo, y, blockIdx.y * 128, blockIdx.x * 128, smem);
}

// ---------------- Attention: one block per (b,h) (unchanged, known-good) ----
#define LDT 132  // Dd + 4

__global__ __launch_bounds__(256) void attn_kernel(const float* __restrict__ gq,
                                                   const float* __restrict__ gk,
                                                   const float* __restrict__ gv,
                                                   float* __restrict__ gatt) {
    extern __shared__ float sm[];
    float* sQ = sm;                    // [128][LDT]  (reused for V)
    float* sK = sm + Ss*LDT;
    float* sS = sm + 2*Ss*LDT;

    const int bh = blockIdx.x;
    const int b  = bh >> 2;
    const int h  = bh & 3;
    const int tid  = threadIdx.x;
    const int warp = tid >> 5;
    const int lane = tid & 31;
    const int g = lane >> 2, t = lane & 3;

    const float* qbase = gq + (size_t)b*Ss*Ee + h*Dd;
    const float* kbase = gk + (size_t)b*Ss*Ee + h*Dd;
    const float* vbase = gv + (size_t)b*Ss*Ee + h*Dd;

    #pragma unroll
    for (int it = 0; it < 16; it++) {
        int idx = tid + it*256;
        int r = idx >> 5, c = (idx & 31) << 2;
        float4 v = *(const float4*)(qbase + (size_t)r*Ee + c);
        float* d = sQ + r*LDT + c;
        d[0]=v.x; d[1]=v.y; d[2]=v.z; d[3]=v.w;
        v = *(const float4*)(kbase + (size_t)r*Ee + c);
        d = sK + r*LDT + c;
        d[0]=v.x; d[1]=v.y; d[2]=v.z; d[3]=v.w;
    }
    __syncthreads();

    float acc[16][4];

    #pragma unroll
    for (int j = 0; j < 16; j++) { acc[j][0]=0.f; acc[j][1]=0.f; acc[j][2]=0.f; acc[j][3]=0.f; }

    for (int kk = 0; kk < Dd; kk += 8) {
        const float* p = sQ + (warp*16 + g)*LDT + kk + t;
        float a0 = p[0], a1 = p[8*LDT], a2 = p[4], a3 = p[8*LDT+4];
        uint32_t ah[4] = { tf32_hi(a0), tf32_hi(a1), tf32_hi(a2), tf32_hi(a3) };
        uint32_t al[4] = { tf32_lo(a0, ah[0]), tf32_lo(a1, ah[1]),
                           tf32_lo(a2, ah[2]), tf32_lo(a3, ah[3]) };
        #pragma unroll
        for (int j = 0; j < 16; j++) {
            const float* q = sK + (j*8 + g)*LDT + kk + t;
            float b0 = q[0], b1 = q[4];
            uint32_t bh[2] = { tf32_hi(b0), tf32_hi(b1) };
            uint32_t bl[2] = { tf32_lo(b0, bh[0]), tf32_lo(b1, bh[1]) };
            mma8(acc[j], ah, bh);
            mma8(acc[j], ah, bl);
            mma8(acc[j], al, bh);
        }
    }
    #pragma unroll
    for (int j = 0; j < 16; j++) {
        float* p = sS + (warp*16 + g)*LDT + j*8 + 2*t;
        *(float2*)p              = { acc[j][0], acc[j][1] };
        *(float2*)(p + 8*LDT)    = { acc[j][2], acc[j][3] };
    }
    __syncthreads();

    float* sV = sQ;
    #pragma unroll
    for (int it = 0; it < 16; it++) {
        int idx = tid + it*256;
        int r = idx >> 5, c = (idx & 31) << 2;
        float4 v = *(const float4*)(vbase + (size_t)r*Ee + c);
        float* d = sV + r*LDT + c;
        d[0]=v.x; d[1]=v.y; d[2]=v.z; d[3]=v.w;
    }

    #pragma unroll 1
    for (int rr = 0; rr < 16; rr++) {
        float* row = sS + (warp*16 + rr)*LDT;
        float v0 = row[lane], v1 = row[lane+32], v2 = row[lane+64], v3 = row[lane+96];
        float m = fmaxf(fmaxf(v0, v1), fmaxf(v2, v3));
        #pragma unroll
        for (int off = 16; off > 0; off >>= 1)
            m = fmaxf(m, __shfl_xor_sync(0xFFFFFFFFu, m, off));
        v0 = __expf(v0 - m); v1 = __expf(v1 - m); v2 = __expf(v2 - m); v3 = __expf(v3 - m);
        float s = v0 + v1 + v2 + v3;
        #pragma unroll
        for (int off = 16; off > 0; off >>= 1)
            s += __shfl_xor_sync(0xFFFFFFFFu, s, off);
        float inv = 1.0f / s;
        row[lane]    = v0 * inv;
        row[lane+32] = v1 * inv;
        row[lane+64] = v2 * inv;
        row[lane+96] = v3 * inv;
    }
    __syncthreads();

    #pragma unroll
    for (int j = 0; j < 16; j++) { acc[j][0]=0.f; acc[j][1]=0.f; acc[j][2]=0.f; acc[j][3]=0.f; }

    for (int kk = 0; kk < Ss; kk += 8) {
        const float* p = sS + (warp*16 + g)*LDT + kk + t;
        float a0 = p[0], a1 = p[8*LDT], a2 = p[4], a3 = p[8*LDT+4];
        uint32_t ah[4] = { tf32_hi(a0), tf32_hi(a1), tf32_hi(a2), tf32_hi(a3) };
        uint32_t al[4] = { tf32_lo(a0, ah[0]), tf32_lo(a1, ah[1]),
                           tf32_lo(a2, ah[2]), tf32_lo(a3, ah[3]) };
        #pragma unroll
        for (int j = 0; j < 16; j++) {
            const float* q = sV + (kk + t)*LDT + j*8 + g;
            float b0 = q[0], b1 = q[4*LDT];
            uint32_t bh[2] = { tf32_hi(b0), tf32_hi(b1) };
            uint32_t bl[2] = { tf32_lo(b0, bh[0]), tf32_lo(b1, bh[1]) };
            mma8(acc[j], ah, bh);
            mma8(acc[j], ah, bl);
            mma8(acc[j], al, bh);
        }
    }

    #pragma unroll
    for (int j = 0; j < 16; j++) {
        size_t row = (size_t)(b*Ss + warp*16 + g);
        int col = h*Dd + j*8 + 2*t;
        *(float2*)(gatt + row*Ee + col)       = { acc[j][0], acc[j][1] };
        *(float2*)(gatt + (row + 8)*Ee + col) = { acc[j][2], acc[j][3] };
    }
}

// ---------------- Launch ----------------
extern "C" void kernel_launch(void* const* d_in, const int* in_sizes, int n_in,
                              void* d_out, int out_size) {
    const float* x  = (const float*)d_in[0];
    const float* Wq = (const float*)d_in[1];
    const float* bq = (const float*)d_in[2];
    const float* Wk = (const float*)d_in[3];
    const float* bk = (const float*)d_in[4];
    const float* Wv = (const float*)d_in[5];
    const float* bv = (const float*)d_in[6];
    const float* Wo = (const float*)d_in[7];
    const float* bo = (const float*)d_in[8];
    float* y = (float*)d_out;

    float *q, *k, *v, *att;
    cudaGetSymbolAddress((void**)&q,   g_q);
    cudaGetSymbolAddress((void**)&k,   g_k);
    cudaGetSymbolAddress((void**)&v,   g_v);
    cudaGetSymbolAddress((void**)&att, g_att);

    const int attn_smem = 3 * Ss * LDT * (int)sizeof(float);   // 202752 bytes
    cudaFuncSetAttribute(attn_kernel, cudaFuncAttributeMaxDynamicSharedMemorySize, attn_smem);
    cudaFuncSetAttribute(qkv_kernel,  cudaFuncAttributeMaxDynamicSharedMemorySize, GEMM_SMEM);
    cudaFuncSetAttribute(out_kernel,  cudaFuncAttributeMaxDynamicSharedMemorySize, GEMM_SMEM);

    dim3 gqkv(12, Mtot/128);           // 3 mats x 4 N-tiles, x fastest
    qkv_kernel<<<gqkv, 256, GEMM_SMEM>>>(x, Wq, bq, Wk, bk, Wv, bv, q, k, v);

    attn_kernel<<<Bb*Hh, 256, attn_smem>>>(q, k, v, att);

    dim3 gout(Ee/128, Mtot/128);
    out_kernel<<<gout, 256, GEMM_SMEM>>>(att, Wo, bo, y);
}